// round 14
// baseline (speedup 1.0000x reference)
#include <cuda_runtime.h>
#include <cuda_bf16.h>

// SwinMSA fused kernel — round 6: tensor-core GEMMs (split-bf16 3-product mma).
// B=16, WN=4096, S=10, E=96, H=4, dh=24.  WPB=4 windows/CTA, 288 threads (9 warps).
//   prep:    split Wqkv/Wo into bf16 hi/lo, k-major, once per launch
//   phase 1: qkv = X @ W_qkv + b   via mma.m16n8k16 (AhBh + AhBl + AlBh)
//   phase 2: attention (scalar fp32, proven), writes split-bf16 context
//   phase 3: out = ctx @ W_o + b_o via mma

#define S_    10
#define E_    96
#define H_    4
#define DH_   24
#define N3_   288
#define WPB   4
#define ROWS  40              // WPB * S_
#define MROWS 48              // padded to 3 m-tiles of 16
#define KA    104             // bf16 row stride of A tiles (conflict-free frag loads)
#define PAD   25
#define WN_   4096
#define NTHREADS 288
#define QSCALE 0.20412414523193154f   // 24^-0.5

typedef unsigned u32;

// weight splits (set by prep kernel each launch; layout k-major: [n][k])
__device__ __nv_bfloat16 g_WqkvH[E_ * N3_];
__device__ __nv_bfloat16 g_WqkvL[E_ * N3_];
__device__ __nv_bfloat16 g_WoH[E_ * E_];
__device__ __nv_bfloat16 g_WoL[E_ * E_];

__global__ void prep_split(const float* __restrict__ Wqkv, const float* __restrict__ Wo)
{
    const int i = blockIdx.x * blockDim.x + threadIdx.x;
    if (i < E_ * N3_) {
        const int n = i / E_, k = i - n * E_;
        const float w = Wqkv[k * N3_ + n];
        const __nv_bfloat16 h = __float2bfloat16(w);
        g_WqkvH[i] = h;
        g_WqkvL[i] = __float2bfloat16(w - __bfloat162float(h));
    }
    if (i < E_ * E_) {
        const int n = i / E_, k = i - n * E_;
        const float w = Wo[k * E_ + n];
        const __nv_bfloat16 h = __float2bfloat16(w);
        g_WoH[i] = h;
        g_WoL[i] = __float2bfloat16(w - __bfloat162float(h));
    }
}

__device__ __forceinline__ void mma_bf16(float d[4], const u32 a[4], const u32 b0, const u32 b1)
{
    asm volatile("mma.sync.aligned.m16n8k16.row.col.f32.bf16.bf16.f32 "
                 "{%0,%1,%2,%3}, {%4,%5,%6,%7}, {%8,%9}, {%0,%1,%2,%3};"
                 : "+f"(d[0]), "+f"(d[1]), "+f"(d[2]), "+f"(d[3])
                 : "r"(a[0]), "r"(a[1]), "r"(a[2]), "r"(a[3]), "r"(b0), "r"(b1));
}

__device__ __forceinline__ unsigned short bfu(__nv_bfloat16 x) { return __bfloat16_as_ushort(x); }

#define SMEM_BYTES (2 * MROWS * KA * 2 + 3 * 16 * S_ * PAD * 4 + 80 * 4)

__global__ __launch_bounds__(NTHREADS, 2)
void swin_msa_kernel(const float* __restrict__ X,
                     const float* __restrict__ bqkv,
                     const float* __restrict__ bo,
                     const float* __restrict__ posb,
                     float* __restrict__ out)
{
    extern __shared__ char smem_raw[];
    __nv_bfloat16* sAh = (__nv_bfloat16*)smem_raw;               // [MROWS][KA]
    __nv_bfloat16* sAl = sAh + MROWS * KA;
    float* sQ  = (float*)(smem_raw + 2 * MROWS * KA * 2);        // [16][S_][PAD]
    float* sK  = sQ + 16 * S_ * PAD;
    float* sV  = sK + 16 * S_ * PAD;
    float* spb = sV + 16 * S_ * PAD;                             // 76 floats

    const int tid = threadIdx.x;
    const long wbase = (long)blockIdx.x * WPB;

    // ---- load X (coalesced float4), split to bf16 hi/lo in smem; zero pad rows ----
    {
        const float4* gX4 = (const float4*)(X + wbase * (S_ * E_));
        for (int i = tid; i < ROWS * E_ / 4; i += NTHREADS) {
            const int r  = i / (E_ / 4);
            const int kq = i - r * (E_ / 4);
            const float4 v = gX4[i];
            const __nv_bfloat16 h0 = __float2bfloat16(v.x);
            const __nv_bfloat16 h1 = __float2bfloat16(v.y);
            const __nv_bfloat16 h2 = __float2bfloat16(v.z);
            const __nv_bfloat16 h3 = __float2bfloat16(v.w);
            const __nv_bfloat16 l0 = __float2bfloat16(v.x - __bfloat162float(h0));
            const __nv_bfloat16 l1 = __float2bfloat16(v.y - __bfloat162float(h1));
            const __nv_bfloat16 l2 = __float2bfloat16(v.z - __bfloat162float(h2));
            const __nv_bfloat16 l3 = __float2bfloat16(v.w - __bfloat162float(h3));
            const u32 hA = (u32)bfu(h0) | ((u32)bfu(h1) << 16);
            const u32 hB = (u32)bfu(h2) | ((u32)bfu(h3) << 16);
            const u32 lA = (u32)bfu(l0) | ((u32)bfu(l1) << 16);
            const u32 lB = (u32)bfu(l2) | ((u32)bfu(l3) << 16);
            *(uint2*)&sAh[r * KA + 4 * kq] = make_uint2(hA, hB);
            *(uint2*)&sAl[r * KA + 4 * kq] = make_uint2(lA, lB);
        }
        // zero pad rows 40..47 of both A tiles (208 u64 each)
        for (int i = tid; i < 416; i += NTHREADS) {
            unsigned long long* p = (i < 208)
                ? (unsigned long long*)(sAh + ROWS * KA)
                : (unsigned long long*)(sAl + ROWS * KA);
            p[i % 208] = 0ull;
        }
        if (tid < (2 * S_ - 1) * H_) spb[tid] = posb[tid];
    }
    __syncthreads();

    const int warp = tid >> 5;
    const int lane = tid & 31;
    const int g = lane >> 2;          // fragment group row
    const int t = lane & 3;           // thread in group

    // ---- phase 1: qkv = X @ Wqkv + b  (warp = m-tile mi x 96-col strip ns) ----
    {
        const int mi = warp % 3;
        const int ns = warp / 3;
        float c[12][4];
        #pragma unroll
        for (int nt = 0; nt < 12; nt++)
            #pragma unroll
            for (int i = 0; i < 4; i++) c[nt][i] = 0.0f;

        #pragma unroll
        for (int ks = 0; ks < 6; ks++) {
            const int k0 = 16 * ks + 2 * t;
            const int ra = 16 * mi + g;
            u32 ah[4], al[4];
            ah[0] = *(const u32*)&sAh[ra * KA + k0];
            ah[1] = *(const u32*)&sAh[(ra + 8) * KA + k0];
            ah[2] = *(const u32*)&sAh[ra * KA + k0 + 8];
            ah[3] = *(const u32*)&sAh[(ra + 8) * KA + k0 + 8];
            al[0] = *(const u32*)&sAl[ra * KA + k0];
            al[1] = *(const u32*)&sAl[(ra + 8) * KA + k0];
            al[2] = *(const u32*)&sAl[ra * KA + k0 + 8];
            al[3] = *(const u32*)&sAl[(ra + 8) * KA + k0 + 8];
            #pragma unroll 4
            for (int nt = 0; nt < 12; nt++) {
                const int n = 96 * ns + 8 * nt + g;
                const __nv_bfloat16* bh = &g_WqkvH[n * E_ + k0];
                const __nv_bfloat16* bl = &g_WqkvL[n * E_ + k0];
                const u32 bh0 = *(const u32*)bh, bh1 = *(const u32*)(bh + 8);
                const u32 bl0 = *(const u32*)bl, bl1 = *(const u32*)(bl + 8);
                mma_bf16(c[nt], ah, bh0, bh1);
                mma_bf16(c[nt], ah, bl0, bl1);
                mma_bf16(c[nt], al, bh0, bh1);
            }
        }

        // epilogue: +bias, scatter to sQ/sK/sV  (c0:(g,2t) c1:(g,2t+1) c2:(g+8,2t) c3:(g+8,2t+1))
        #pragma unroll
        for (int nt = 0; nt < 12; nt++) {
            const int colb = 96 * ns + 8 * nt + 2 * t;
            const float2 bb = *(const float2*)&bqkv[colb];
            #pragma unroll
            for (int i = 0; i < 4; i++) {
                const int row = 16 * mi + g + ((i >> 1) << 3);
                if (row >= ROWS) continue;
                const int col = colb + (i & 1);
                float val = c[nt][i] + ((i & 1) ? bb.y : bb.x);
                const int p = col / E_;
                const int rem = col - p * E_;
                const int h = rem / DH_;
                const int d = rem - h * DH_;
                const int wi = row / S_, r = row - wi * S_;
                const int wh = wi * H_ + h;
                if (p == 0)      sQ[(wh * S_ + r) * PAD + d] = val * QSCALE;
                else if (p == 1) sK[(wh * S_ + r) * PAD + d] = val;
                else             sV[(wh * S_ + r) * PAD + d] = val;
            }
        }
    }
    __syncthreads();

    // ---- phase 2: attention, thread = (wi, h, q); writes split-bf16 ctx into sAh/sAl ----
    if (tid < 16 * S_) {
        const int wi = tid / (H_ * S_);
        const int rem = tid - wi * (H_ * S_);
        const int h = rem / S_;
        const int q = rem - h * S_;

        const float* qrow = &sQ[((wi * H_ + h) * S_ + q) * PAD];
        float qv[DH_];
        #pragma unroll
        for (int d = 0; d < DH_; d++) qv[d] = qrow[d];

        const bool masked = (((wbase + wi) & (WN_ - 1)) == (WN_ - 1));

        float row[S_];
        #pragma unroll
        for (int kk = 0; kk < S_; kk++) {
            const float* krow = &sK[((wi * H_ + h) * S_ + kk) * PAD];
            float s = 0.0f;
            #pragma unroll
            for (int d = 0; d < DH_; d++) s += qv[d] * krow[d];
            s += spb[(kk - q + S_ - 1) * H_ + h];
            if (masked && ((q < 5) != (kk < 5))) s -= 100.0f;
            row[kk] = s;
        }

        float m = row[0];
        #pragma unroll
        for (int kk = 1; kk < S_; kk++) m = fmaxf(m, row[kk]);
        float sum = 0.0f;
        #pragma unroll
        for (int kk = 0; kk < S_; kk++) { row[kk] = __expf(row[kk] - m); sum += row[kk]; }
        const float inv = 1.0f / sum;

        const float* vbase = &sV[(wi * H_ + h) * S_ * PAD];
        const int crow = wi * S_ + q;
        #pragma unroll
        for (int d = 0; d < DH_; d++) {
            float o = 0.0f;
            #pragma unroll
            for (int kk = 0; kk < S_; kk++) o += row[kk] * vbase[kk * PAD + d];
            o *= inv;
            const __nv_bfloat16 oh = __float2bfloat16(o);
            sAh[crow * KA + h * DH_ + d] = oh;
            sAl[crow * KA + h * DH_ + d] = __float2bfloat16(o - __bfloat162float(oh));
        }
    }
    __syncthreads();

    // ---- phase 3: out = ctx @ Wo + b  (warp = m-tile mi x 32-col strip ns) ----
    {
        const int mi = warp % 3;
        const int ns = warp / 3;
        float c[4][4];
        #pragma unroll
        for (int nt = 0; nt < 4; nt++)
            #pragma unroll
            for (int i = 0; i < 4; i++) c[nt][i] = 0.0f;

        #pragma unroll
        for (int ks = 0; ks < 6; ks++) {
            const int k0 = 16 * ks + 2 * t;
            const int ra = 16 * mi + g;
            u32 ah[4], al[4];
            ah[0] = *(const u32*)&sAh[ra * KA + k0];
            ah[1] = *(const u32*)&sAh[(ra + 8) * KA + k0];
            ah[2] = *(const u32*)&sAh[ra * KA + k0 + 8];
            ah[3] = *(const u32*)&sAh[(ra + 8) * KA + k0 + 8];
            al[0] = *(const u32*)&sAl[ra * KA + k0];
            al[1] = *(const u32*)&sAl[(ra + 8) * KA + k0];
            al[2] = *(const u32*)&sAl[ra * KA + k0 + 8];
            al[3] = *(const u32*)&sAl[(ra + 8) * KA + k0 + 8];
            #pragma unroll
            for (int nt = 0; nt < 4; nt++) {
                const int n = 32 * ns + 8 * nt + g;
                const __nv_bfloat16* bh = &g_WoH[n * E_ + k0];
                const __nv_bfloat16* bl = &g_WoL[n * E_ + k0];
                const u32 bh0 = *(const u32*)bh, bh1 = *(const u32*)(bh + 8);
                const u32 bl0 = *(const u32*)bl, bl1 = *(const u32*)(bl + 8);
                mma_bf16(c[nt], ah, bh0, bh1);
                mma_bf16(c[nt], ah, bl0, bl1);
                mma_bf16(c[nt], al, bh0, bh1);
            }
        }

        float* gout = out + wbase * (S_ * E_);
        #pragma unroll
        for (int nt = 0; nt < 4; nt++) {
            const int colb = 32 * ns + 8 * nt + 2 * t;
            const float2 bb = *(const float2*)&bo[colb];
            const int row0 = 16 * mi + g;
            if (row0 < ROWS)
                *(float2*)&gout[row0 * E_ + colb] =
                    make_float2(c[nt][0] + bb.x, c[nt][1] + bb.y);
            const int row1 = row0 + 8;
            if (row1 < ROWS)
                *(float2*)&gout[row1 * E_ + colb] =
                    make_float2(c[nt][2] + bb.x, c[nt][3] + bb.y);
        }
    }
}

extern "C" void kernel_launch(void* const* d_in, const int* in_sizes, int n_in,
                              void* d_out, int out_size)
{
    const float* X    = (const float*)d_in[0];
    const float* Wqkv = (const float*)d_in[1];
    const float* bqkv = (const float*)d_in[2];
    const float* Wo   = (const float*)d_in[3];
    const float* bo   = (const float*)d_in[4];
    const float* posb = (const float*)d_in[5];
    float* out = (float*)d_out;

    // split weights to bf16 hi/lo (same stream -> ordered before main kernel)
    prep_split<<<(E_ * N3_ + 255) / 256, 256>>>(Wqkv, Wo);

    cudaFuncSetAttribute(swin_msa_kernel,
                         cudaFuncAttributeMaxDynamicSharedMemorySize, SMEM_BYTES);

    const int n_windows = in_sizes[0] / (S_ * E_);   // 65536
    const int grid = n_windows / WPB;                // 16384
    swin_msa_kernel<<<grid, NTHREADS, SMEM_BYTES>>>(X, bqkv, bo, posb, out);
}

// round 15
// speedup vs baseline: 1.0076x; 1.0076x over previous
#include <cuda_runtime.h>
#include <cuda_bf16.h>

// SwinMSA fused kernel — round 7: tensor-core GEMMs with smem-staged weights.
// B=16, WN=4096, S=10, E=96, H=4, dh=24.  WPB=4 windows/CTA, 288 threads (9 warps).
//   prep:    split Wqkv/Wo into bf16 hi/lo, k-major, once per launch
//   phase 1: qkv = X @ W_qkv + b   via mma.m16n8k16 (AhBh + AhBl + AlBh), B staged in smem
//   phase 2: attention (scalar fp32, proven), writes split-bf16 context
//   phase 3: out = ctx @ W_o + b_o via mma, B staged in smem

#define S_    10
#define E_    96
#define H_    4
#define DH_   24
#define N3_   288
#define WPB   4
#define ROWS  40              // WPB * S_
#define MROWS 48              // padded to 3 m-tiles of 16
#define KA    104             // bf16 row stride of A tiles (conflict-free frag loads)
#define KB    24              // bf16 row stride of staged B tiles (conflict-free)
#define PAD   25
#define WN_   4096
#define NTHREADS 288
#define QSCALE 0.20412414523193154f   // 24^-0.5

typedef unsigned u32;

// weight splits (set by prep kernel each launch; layout k-major: [n][k])
__device__ __nv_bfloat16 g_WqkvH[E_ * N3_];
__device__ __nv_bfloat16 g_WqkvL[E_ * N3_];
__device__ __nv_bfloat16 g_WoH[E_ * E_];
__device__ __nv_bfloat16 g_WoL[E_ * E_];

__global__ void prep_split(const float* __restrict__ Wqkv, const float* __restrict__ Wo)
{
    const int i = blockIdx.x * blockDim.x + threadIdx.x;
    if (i < E_ * N3_) {
        const int n = i / E_, k = i - n * E_;
        const float w = Wqkv[k * N3_ + n];
        const __nv_bfloat16 h = __float2bfloat16(w);
        g_WqkvH[i] = h;
        g_WqkvL[i] = __float2bfloat16(w - __bfloat162float(h));
    }
    if (i < E_ * E_) {
        const int n = i / E_, k = i - n * E_;
        const float w = Wo[k * E_ + n];
        const __nv_bfloat16 h = __float2bfloat16(w);
        g_WoH[i] = h;
        g_WoL[i] = __float2bfloat16(w - __bfloat162float(h));
    }
}

__device__ __forceinline__ void mma_bf16(float d[4], const u32 a[4], const u32 b0, const u32 b1)
{
    asm volatile("mma.sync.aligned.m16n8k16.row.col.f32.bf16.bf16.f32 "
                 "{%0,%1,%2,%3}, {%4,%5,%6,%7}, {%8,%9}, {%0,%1,%2,%3};"
                 : "+f"(d[0]), "+f"(d[1]), "+f"(d[2]), "+f"(d[3])
                 : "r"(a[0]), "r"(a[1]), "r"(a[2]), "r"(a[3]), "r"(b0), "r"(b1));
}

__device__ __forceinline__ unsigned short bfu(__nv_bfloat16 x) { return __bfloat16_as_ushort(x); }

// smem: A hi/lo + B-stage hi/lo + QKV fp32 + posbias
#define SMEM_BYTES (2 * MROWS * KA * 2 + 2 * N3_ * KB * 2 + 3 * 16 * S_ * PAD * 4 + 80 * 4)

__global__ __launch_bounds__(NTHREADS, 2)
void swin_msa_kernel(const float* __restrict__ X,
                     const float* __restrict__ bqkv,
                     const float* __restrict__ bo,
                     const float* __restrict__ posb,
                     float* __restrict__ out)
{
    extern __shared__ char smem_raw[];
    __nv_bfloat16* sAh = (__nv_bfloat16*)smem_raw;               // [MROWS][KA]
    __nv_bfloat16* sAl = sAh + MROWS * KA;
    __nv_bfloat16* sBh = sAl + MROWS * KA;                       // [N3_][KB] staged k-slice
    __nv_bfloat16* sBl = sBh + N3_ * KB;
    float* sQ  = (float*)(sBl + N3_ * KB);                       // [16][S_][PAD]
    float* sK  = sQ + 16 * S_ * PAD;
    float* sV  = sK + 16 * S_ * PAD;
    float* spb = sV + 16 * S_ * PAD;                             // 76 floats

    const int tid = threadIdx.x;
    const long wbase = (long)blockIdx.x * WPB;

    // ---- load X (coalesced float4), split to bf16 hi/lo in smem; zero pad rows ----
    {
        const float4* gX4 = (const float4*)(X + wbase * (S_ * E_));
        for (int i = tid; i < ROWS * E_ / 4; i += NTHREADS) {
            const int r  = i / (E_ / 4);
            const int kq = i - r * (E_ / 4);
            const float4 v = gX4[i];
            const __nv_bfloat16 h0 = __float2bfloat16(v.x);
            const __nv_bfloat16 h1 = __float2bfloat16(v.y);
            const __nv_bfloat16 h2 = __float2bfloat16(v.z);
            const __nv_bfloat16 h3 = __float2bfloat16(v.w);
            const __nv_bfloat16 l0 = __float2bfloat16(v.x - __bfloat162float(h0));
            const __nv_bfloat16 l1 = __float2bfloat16(v.y - __bfloat162float(h1));
            const __nv_bfloat16 l2 = __float2bfloat16(v.z - __bfloat162float(h2));
            const __nv_bfloat16 l3 = __float2bfloat16(v.w - __bfloat162float(h3));
            const u32 hA = (u32)bfu(h0) | ((u32)bfu(h1) << 16);
            const u32 hB = (u32)bfu(h2) | ((u32)bfu(h3) << 16);
            const u32 lA = (u32)bfu(l0) | ((u32)bfu(l1) << 16);
            const u32 lB = (u32)bfu(l2) | ((u32)bfu(l3) << 16);
            *(uint2*)&sAh[r * KA + 4 * kq] = make_uint2(hA, hB);
            *(uint2*)&sAl[r * KA + 4 * kq] = make_uint2(lA, lB);
        }
        // zero pad rows 40..47 of both A tiles (208 u64 each)
        for (int i = tid; i < 416; i += NTHREADS) {
            unsigned long long* p = (i < 208)
                ? (unsigned long long*)(sAh + ROWS * KA)
                : (unsigned long long*)(sAl + ROWS * KA);
            p[i % 208] = 0ull;
        }
        if (tid < (2 * S_ - 1) * H_) spb[tid] = posb[tid];
    }
    __syncthreads();

    const int warp = tid >> 5;
    const int lane = tid & 31;
    const int g = lane >> 2;          // fragment group row
    const int t = lane & 3;           // thread in group

    // ---- phase 1: qkv = X @ Wqkv + b  (warp = m-tile mi x 96-col strip ns) ----
    {
        const int mi = warp % 3;
        const int ns = warp / 3;
        float c[12][4];
        #pragma unroll
        for (int nt = 0; nt < 12; nt++)
            #pragma unroll
            for (int i = 0; i < 4; i++) c[nt][i] = 0.0f;

        for (int ks = 0; ks < 6; ks++) {
            // stage B k-slice [288 n][16 k] hi+lo into smem (thread = one n row)
            {
                const uint4* srcH = (const uint4*)&g_WqkvH[tid * E_ + 16 * ks];
                const uint4* srcL = (const uint4*)&g_WqkvL[tid * E_ + 16 * ks];
                const uint4 h0 = srcH[0], h1 = srcH[1];
                const uint4 l0 = srcL[0], l1 = srcL[1];
                *(uint4*)&sBh[tid * KB]     = h0;
                *(uint4*)&sBh[tid * KB + 8] = h1;
                *(uint4*)&sBl[tid * KB]     = l0;
                *(uint4*)&sBl[tid * KB + 8] = l1;
            }
            __syncthreads();

            const int k0 = 16 * ks + 2 * t;
            const int kr = 2 * t;                 // k offset within staged slice
            const int ra = 16 * mi + g;
            u32 ah[4], al[4];
            ah[0] = *(const u32*)&sAh[ra * KA + k0];
            ah[1] = *(const u32*)&sAh[(ra + 8) * KA + k0];
            ah[2] = *(const u32*)&sAh[ra * KA + k0 + 8];
            ah[3] = *(const u32*)&sAh[(ra + 8) * KA + k0 + 8];
            al[0] = *(const u32*)&sAl[ra * KA + k0];
            al[1] = *(const u32*)&sAl[(ra + 8) * KA + k0];
            al[2] = *(const u32*)&sAl[ra * KA + k0 + 8];
            al[3] = *(const u32*)&sAl[(ra + 8) * KA + k0 + 8];
            #pragma unroll 4
            for (int nt = 0; nt < 12; nt++) {
                const int n = 96 * ns + 8 * nt + g;
                const __nv_bfloat16* bh = &sBh[n * KB + kr];
                const __nv_bfloat16* bl = &sBl[n * KB + kr];
                const u32 bh0 = *(const u32*)bh, bh1 = *(const u32*)(bh + 8);
                const u32 bl0 = *(const u32*)bl, bl1 = *(const u32*)(bl + 8);
                mma_bf16(c[nt], ah, bh0, bh1);
                mma_bf16(c[nt], ah, bl0, bl1);
                mma_bf16(c[nt], al, bh0, bh1);
            }
            __syncthreads();
        }

        // epilogue: +bias, scatter to sQ/sK/sV  (c0:(g,2t) c1:(g,2t+1) c2:(g+8,2t) c3:(g+8,2t+1))
        #pragma unroll
        for (int nt = 0; nt < 12; nt++) {
            const int colb = 96 * ns + 8 * nt + 2 * t;
            const float2 bb = *(const float2*)&bqkv[colb];
            #pragma unroll
            for (int i = 0; i < 4; i++) {
                const int row = 16 * mi + g + ((i >> 1) << 3);
                if (row >= ROWS) continue;
                const int col = colb + (i & 1);
                float val = c[nt][i] + ((i & 1) ? bb.y : bb.x);
                const int p = col / E_;
                const int rem = col - p * E_;
                const int h = rem / DH_;
                const int d = rem - h * DH_;
                const int wi = row / S_, r = row - wi * S_;
                const int wh = wi * H_ + h;
                if (p == 0)      sQ[(wh * S_ + r) * PAD + d] = val * QSCALE;
                else if (p == 1) sK[(wh * S_ + r) * PAD + d] = val;
                else             sV[(wh * S_ + r) * PAD + d] = val;
            }
        }
    }
    __syncthreads();

    // ---- phase 2: attention, thread = (wi, h, q); writes split-bf16 ctx into sAh/sAl ----
    if (tid < 16 * S_) {
        const int wi = tid / (H_ * S_);
        const int rem = tid - wi * (H_ * S_);
        const int h = rem / S_;
        const int q = rem - h * S_;

        const float* qrow = &sQ[((wi * H_ + h) * S_ + q) * PAD];
        float qv[DH_];
        #pragma unroll
        for (int d = 0; d < DH_; d++) qv[d] = qrow[d];

        const bool masked = (((wbase + wi) & (WN_ - 1)) == (WN_ - 1));

        float row[S_];
        #pragma unroll
        for (int kk = 0; kk < S_; kk++) {
            const float* krow = &sK[((wi * H_ + h) * S_ + kk) * PAD];
            float s = 0.0f;
            #pragma unroll
            for (int d = 0; d < DH_; d++) s += qv[d] * krow[d];
            s += spb[(kk - q + S_ - 1) * H_ + h];
            if (masked && ((q < 5) != (kk < 5))) s -= 100.0f;
            row[kk] = s;
        }

        float m = row[0];
        #pragma unroll
        for (int kk = 1; kk < S_; kk++) m = fmaxf(m, row[kk]);
        float sum = 0.0f;
        #pragma unroll
        for (int kk = 0; kk < S_; kk++) { row[kk] = __expf(row[kk] - m); sum += row[kk]; }
        const float inv = 1.0f / sum;

        const float* vbase = &sV[(wi * H_ + h) * S_ * PAD];
        const int crow = wi * S_ + q;
        #pragma unroll
        for (int d = 0; d < DH_; d++) {
            float o = 0.0f;
            #pragma unroll
            for (int kk = 0; kk < S_; kk++) o += row[kk] * vbase[kk * PAD + d];
            o *= inv;
            const __nv_bfloat16 oh = __float2bfloat16(o);
            sAh[crow * KA + h * DH_ + d] = oh;
            sAl[crow * KA + h * DH_ + d] = __float2bfloat16(o - __bfloat162float(oh));
        }
    }
    __syncthreads();

    // ---- phase 3: out = ctx @ Wo + b  (warp = m-tile mi x 32-col strip ns) ----
    {
        const int mi = warp % 3;
        const int ns = warp / 3;
        float c[4][4];
        #pragma unroll
        for (int nt = 0; nt < 4; nt++)
            #pragma unroll
            for (int i = 0; i < 4; i++) c[nt][i] = 0.0f;

        for (int ks = 0; ks < 6; ks++) {
            // stage Wo k-slice [96 n][16 k] hi+lo (threads 0..95 hi, 96..191 lo)
            if (tid < 192) {
                const int n = tid % 96;
                if (tid < 96) {
                    const uint4* src = (const uint4*)&g_WoH[n * E_ + 16 * ks];
                    const uint4 a = src[0], b = src[1];
                    *(uint4*)&sBh[n * KB]     = a;
                    *(uint4*)&sBh[n * KB + 8] = b;
                } else {
                    const uint4* src = (const uint4*)&g_WoL[n * E_ + 16 * ks];
                    const uint4 a = src[0], b = src[1];
                    *(uint4*)&sBl[n * KB]     = a;
                    *(uint4*)&sBl[n * KB + 8] = b;
                }
            }
            __syncthreads();

            const int k0 = 16 * ks + 2 * t;
            const int kr = 2 * t;
            const int ra = 16 * mi + g;
            u32 ah[4], al[4];
            ah[0] = *(const u32*)&sAh[ra * KA + k0];
            ah[1] = *(const u32*)&sAh[(ra + 8) * KA + k0];
            ah[2] = *(const u32*)&sAh[ra * KA + k0 + 8];
            ah[3] = *(const u32*)&sAh[(ra + 8) * KA + k0 + 8];
            al[0] = *(const u32*)&sAl[ra * KA + k0];
            al[1] = *(const u32*)&sAl[(ra + 8) * KA + k0];
            al[2] = *(const u32*)&sAl[ra * KA + k0 + 8];
            al[3] = *(const u32*)&sAl[(ra + 8) * KA + k0 + 8];
            #pragma unroll
            for (int nt = 0; nt < 4; nt++) {
                const int n = 32 * ns + 8 * nt + g;
                const __nv_bfloat16* bh = &sBh[n * KB + kr];
                const __nv_bfloat16* bl = &sBl[n * KB + kr];
                const u32 bh0 = *(const u32*)bh, bh1 = *(const u32*)(bh + 8);
                const u32 bl0 = *(const u32*)bl, bl1 = *(const u32*)(bl + 8);
                mma_bf16(c[nt], ah, bh0, bh1);
                mma_bf16(c[nt], ah, bl0, bl1);
                mma_bf16(c[nt], al, bh0, bh1);
            }
            __syncthreads();
        }

        float* gout = out + wbase * (S_ * E_);
        #pragma unroll
        for (int nt = 0; nt < 4; nt++) {
            const int colb = 32 * ns + 8 * nt + 2 * t;
            const float2 bb = *(const float2*)&bo[colb];
            const int row0 = 16 * mi + g;
            if (row0 < ROWS)
                *(float2*)&gout[row0 * E_ + colb] =
                    make_float2(c[nt][0] + bb.x, c[nt][1] + bb.y);
            const int row1 = row0 + 8;
            if (row1 < ROWS)
                *(float2*)&gout[row1 * E_ + colb] =
                    make_float2(c[nt][2] + bb.x, c[nt][3] + bb.y);
        }
    }
}

extern "C" void kernel_launch(void* const* d_in, const int* in_sizes, int n_in,
                              void* d_out, int out_size)
{
    const float* X    = (const float*)d_in[0];
    const float* Wqkv = (const float*)d_in[1];
    const float* bqkv = (const float*)d_in[2];
    const float* Wo   = (const float*)d_in[3];
    const float* bo   = (const float*)d_in[4];
    const float* posb = (const float*)d_in[5];
    float* out = (float*)d_out;

    // split weights to bf16 hi/lo (same stream -> ordered before main kernel)
    prep_split<<<(E_ * N3_ + 255) / 256, 256>>>(Wqkv, Wo);

    cudaFuncSetAttribute(swin_msa_kernel,
                         cudaFuncAttributeMaxDynamicSharedMemorySize, SMEM_BYTES);

    const int n_windows = in_sizes[0] / (S_ * E_);   // 65536
    const int grid = n_windows / WPB;                // 16384
    swin_msa_kernel<<<grid, NTHREADS, SMEM_BYTES>>>(X, bqkv, bo, posb, out);
}

// round 16
// speedup vs baseline: 1.0561x; 1.0482x over previous
#include <cuda_runtime.h>
#include <cuda_bf16.h>

// SwinMSA fused kernel — round 8: persistent CTAs, ALL split weights resident in smem.
// B=16, WN=4096, S=10, E=96, H=4, dh=24.
// 1024 persistent CTAs (288 threads, 1 CTA/SM via 222KB smem), grid-stride over
// 16384 groups of WPB=4 windows:
//   prep:    split Wqkv/Wo into bf16 hi/lo, k-major padded stride 104, once per launch
//   init:    copy all weights (156KB) global -> smem once per CTA
//   per group:
//     phase 1: qkv = X @ W_qkv + b   via mma.m16n8k16 (AhBh + AhBl + AlBh), sync-free
//     phase 2: attention (scalar fp32), writes split-bf16 context
//     phase 3: out = ctx @ W_o + b_o via mma

#define S_    10
#define E_    96
#define H_    4
#define DH_   24
#define N3_   288
#define WPB   4
#define ROWS  40              // WPB * S_
#define MROWS 48              // padded to 3 m-tiles of 16
#define KA    104             // bf16 row stride of A tiles (conflict-free frag loads)
#define KW    104             // bf16 row stride of resident weights (conflict-free)
#define PAD   25
#define WN_   4096
#define NTHREADS 288
#define QSCALE 0.20412414523193154f   // 24^-0.5

typedef unsigned u32;

// packed split weights, k-major stride KW:  [WqkvH | WqkvL | WoH | WoL]
#define OFF_QKV_H 0
#define OFF_QKV_L (N3_ * KW)
#define OFF_WO_H  (2 * N3_ * KW)
#define OFF_WO_L  (2 * N3_ * KW + E_ * KW)
#define W_TOTAL   (2 * N3_ * KW + 2 * E_ * KW)     // 79872 bf16 = 159744 B

__device__ __nv_bfloat16 g_W[W_TOTAL];

__global__ void prep_split(const float* __restrict__ Wqkv, const float* __restrict__ Wo)
{
    const int i = blockIdx.x * blockDim.x + threadIdx.x;
    if (i < N3_ * KW) {
        const int n = i / KW, k = i - n * KW;
        float w = (k < E_) ? Wqkv[k * N3_ + n] : 0.0f;
        const __nv_bfloat16 h = __float2bfloat16(w);
        g_W[OFF_QKV_H + i] = h;
        g_W[OFF_QKV_L + i] = __float2bfloat16(w - __bfloat162float(h));
    }
    if (i < E_ * KW) {
        const int n = i / KW, k = i - n * KW;
        float w = (k < E_) ? Wo[k * E_ + n] : 0.0f;
        const __nv_bfloat16 h = __float2bfloat16(w);
        g_W[OFF_WO_H + i] = h;
        g_W[OFF_WO_L + i] = __float2bfloat16(w - __bfloat162float(h));
    }
}

__device__ __forceinline__ void mma_bf16(float d[4], const u32 a[4], const u32 b0, const u32 b1)
{
    asm volatile("mma.sync.aligned.m16n8k16.row.col.f32.bf16.bf16.f32 "
                 "{%0,%1,%2,%3}, {%4,%5,%6,%7}, {%8,%9}, {%0,%1,%2,%3};"
                 : "+f"(d[0]), "+f"(d[1]), "+f"(d[2]), "+f"(d[3])
                 : "r"(a[0]), "r"(a[1]), "r"(a[2]), "r"(a[3]), "r"(b0), "r"(b1));
}

__device__ __forceinline__ unsigned short bfu(__nv_bfloat16 x) { return __bfloat16_as_ushort(x); }

// smem: resident weights + A hi/lo + QKV fp32 + posbias
#define SMEM_BYTES (W_TOTAL * 2 + 2 * MROWS * KA * 2 + 3 * 16 * S_ * PAD * 4 + 80 * 4)

__global__ __launch_bounds__(NTHREADS, 1)
void swin_msa_kernel(const float* __restrict__ X,
                     const float* __restrict__ bqkv,
                     const float* __restrict__ bo,
                     const float* __restrict__ posb,
                     float* __restrict__ out,
                     int n_groups)
{
    extern __shared__ char smem_raw[];
    __nv_bfloat16* sW  = (__nv_bfloat16*)smem_raw;               // [W_TOTAL]
    __nv_bfloat16* sAh = sW + W_TOTAL;                           // [MROWS][KA]
    __nv_bfloat16* sAl = sAh + MROWS * KA;
    float* sQ  = (float*)(sAl + MROWS * KA);                     // [16][S_][PAD]
    float* sK  = sQ + 16 * S_ * PAD;
    float* sV  = sK + 16 * S_ * PAD;
    float* spb = sV + 16 * S_ * PAD;                             // 76 floats

    const __nv_bfloat16* sWqH = sW + OFF_QKV_H;
    const __nv_bfloat16* sWqL = sW + OFF_QKV_L;
    const __nv_bfloat16* sWoH = sW + OFF_WO_H;
    const __nv_bfloat16* sWoL = sW + OFF_WO_L;

    const int tid = threadIdx.x;

    // ---- one-time init: weights -> smem, pos bias, zero A pad rows ----
    {
        const uint4* src = (const uint4*)g_W;
        uint4* dst = (uint4*)sW;
        for (int i = tid; i < W_TOTAL / 8; i += NTHREADS)
            dst[i] = src[i];
        // zero pad rows 40..47 of both A tiles (208 u64 each)
        for (int i = tid; i < 416; i += NTHREADS) {
            unsigned long long* p = (i < 208)
                ? (unsigned long long*)(sAh + ROWS * KA)
                : (unsigned long long*)(sAl + ROWS * KA);
            p[i % 208] = 0ull;
        }
        if (tid < (2 * S_ - 1) * H_) spb[tid] = posb[tid];
    }

    const int warp = tid >> 5;
    const int lane = tid & 31;
    const int g = lane >> 2;          // fragment group row
    const int t = lane & 3;           // thread in group

    for (int gi = blockIdx.x; gi < n_groups; gi += gridDim.x) {
        const long wbase = (long)gi * WPB;
        __syncthreads();   // weights ready (first iter) / prev phase-3 done with sA

        // ---- load X (coalesced float4), split to bf16 hi/lo in smem ----
        {
            const float4* gX4 = (const float4*)(X + wbase * (S_ * E_));
            for (int i = tid; i < ROWS * E_ / 4; i += NTHREADS) {
                const int r  = i / (E_ / 4);
                const int kq = i - r * (E_ / 4);
                const float4 v = gX4[i];
                const __nv_bfloat16 h0 = __float2bfloat16(v.x);
                const __nv_bfloat16 h1 = __float2bfloat16(v.y);
                const __nv_bfloat16 h2 = __float2bfloat16(v.z);
                const __nv_bfloat16 h3 = __float2bfloat16(v.w);
                const __nv_bfloat16 l0 = __float2bfloat16(v.x - __bfloat162float(h0));
                const __nv_bfloat16 l1 = __float2bfloat16(v.y - __bfloat162float(h1));
                const __nv_bfloat16 l2 = __float2bfloat16(v.z - __bfloat162float(h2));
                const __nv_bfloat16 l3 = __float2bfloat16(v.w - __bfloat162float(h3));
                const u32 hA = (u32)bfu(h0) | ((u32)bfu(h1) << 16);
                const u32 hB = (u32)bfu(h2) | ((u32)bfu(h3) << 16);
                const u32 lA = (u32)bfu(l0) | ((u32)bfu(l1) << 16);
                const u32 lB = (u32)bfu(l2) | ((u32)bfu(l3) << 16);
                *(uint2*)&sAh[r * KA + 4 * kq] = make_uint2(hA, hB);
                *(uint2*)&sAl[r * KA + 4 * kq] = make_uint2(lA, lB);
            }
        }
        __syncthreads();

        // ---- phase 1: qkv = X @ Wqkv + b  (warp = m-tile mi x 96-col strip ns) ----
        {
            const int mi = warp % 3;
            const int ns = warp / 3;
            float c[12][4];
            #pragma unroll
            for (int nt = 0; nt < 12; nt++)
                #pragma unroll
                for (int i = 0; i < 4; i++) c[nt][i] = 0.0f;

            #pragma unroll
            for (int ks = 0; ks < 6; ks++) {
                const int k0 = 16 * ks + 2 * t;
                const int ra = 16 * mi + g;
                u32 ah[4], al[4];
                ah[0] = *(const u32*)&sAh[ra * KA + k0];
                ah[1] = *(const u32*)&sAh[(ra + 8) * KA + k0];
                ah[2] = *(const u32*)&sAh[ra * KA + k0 + 8];
                ah[3] = *(const u32*)&sAh[(ra + 8) * KA + k0 + 8];
                al[0] = *(const u32*)&sAl[ra * KA + k0];
                al[1] = *(const u32*)&sAl[(ra + 8) * KA + k0];
                al[2] = *(const u32*)&sAl[ra * KA + k0 + 8];
                al[3] = *(const u32*)&sAl[(ra + 8) * KA + k0 + 8];
                #pragma unroll 4
                for (int nt = 0; nt < 12; nt++) {
                    const int n = 96 * ns + 8 * nt + g;
                    const __nv_bfloat16* bh = &sWqH[n * KW + k0];
                    const __nv_bfloat16* bl = &sWqL[n * KW + k0];
                    const u32 bh0 = *(const u32*)bh, bh1 = *(const u32*)(bh + 8);
                    const u32 bl0 = *(const u32*)bl, bl1 = *(const u32*)(bl + 8);
                    mma_bf16(c[nt], ah, bh0, bh1);
                    mma_bf16(c[nt], ah, bl0, bl1);
                    mma_bf16(c[nt], al, bh0, bh1);
                }
            }

            // epilogue: +bias, scatter to sQ/sK/sV (c0:(g,2t) c1:(g,2t+1) c2:(g+8,2t) c3:(g+8,2t+1))
            #pragma unroll
            for (int nt = 0; nt < 12; nt++) {
                const int colb = 96 * ns + 8 * nt + 2 * t;
                const float2 bb = *(const float2*)&bqkv[colb];
                #pragma unroll
                for (int i = 0; i < 4; i++) {
                    const int row = 16 * mi + g + ((i >> 1) << 3);
                    if (row >= ROWS) continue;
                    const int col = colb + (i & 1);
                    float val = c[nt][i] + ((i & 1) ? bb.y : bb.x);
                    const int p = col / E_;
                    const int rem = col - p * E_;
                    const int h = rem / DH_;
                    const int d = rem - h * DH_;
                    const int wi = row / S_, r = row - wi * S_;
                    const int wh = wi * H_ + h;
                    if (p == 0)      sQ[(wh * S_ + r) * PAD + d] = val * QSCALE;
                    else if (p == 1) sK[(wh * S_ + r) * PAD + d] = val;
                    else             sV[(wh * S_ + r) * PAD + d] = val;
                }
            }
        }
        __syncthreads();

        // ---- phase 2: attention, thread = (wi, h, q); writes split-bf16 ctx into sAh/sAl ----
        if (tid < 16 * S_) {
            const int wi = tid / (H_ * S_);
            const int rem = tid - wi * (H_ * S_);
            const int h = rem / S_;
            const int q = rem - h * S_;

            const float* qrow = &sQ[((wi * H_ + h) * S_ + q) * PAD];
            float qv[DH_];
            #pragma unroll
            for (int d = 0; d < DH_; d++) qv[d] = qrow[d];

            const bool masked = (((wbase + wi) & (WN_ - 1)) == (WN_ - 1));

            float row[S_];
            #pragma unroll
            for (int kk = 0; kk < S_; kk++) {
                const float* krow = &sK[((wi * H_ + h) * S_ + kk) * PAD];
                float s = 0.0f;
                #pragma unroll
                for (int d = 0; d < DH_; d++) s += qv[d] * krow[d];
                s += spb[(kk - q + S_ - 1) * H_ + h];
                if (masked && ((q < 5) != (kk < 5))) s -= 100.0f;
                row[kk] = s;
            }

            float m = row[0];
            #pragma unroll
            for (int kk = 1; kk < S_; kk++) m = fmaxf(m, row[kk]);
            float sum = 0.0f;
            #pragma unroll
            for (int kk = 0; kk < S_; kk++) { row[kk] = __expf(row[kk] - m); sum += row[kk]; }
            const float inv = 1.0f / sum;

            const float* vbase = &sV[(wi * H_ + h) * S_ * PAD];
            const int crow = wi * S_ + q;
            #pragma unroll
            for (int d = 0; d < DH_; d++) {
                float o = 0.0f;
                #pragma unroll
                for (int kk = 0; kk < S_; kk++) o += row[kk] * vbase[kk * PAD + d];
                o *= inv;
                const __nv_bfloat16 oh = __float2bfloat16(o);
                sAh[crow * KA + h * DH_ + d] = oh;
                sAl[crow * KA + h * DH_ + d] = __float2bfloat16(o - __bfloat162float(oh));
            }
        }
        __syncthreads();

        // ---- phase 3: out = ctx @ Wo + b  (warp = m-tile mi x 32-col strip ns) ----
        {
            const int mi = warp % 3;
            const int ns = warp / 3;
            float c[4][4];
            #pragma unroll
            for (int nt = 0; nt < 4; nt++)
                #pragma unroll
                for (int i = 0; i < 4; i++) c[nt][i] = 0.0f;

            #pragma unroll
            for (int ks = 0; ks < 6; ks++) {
                const int k0 = 16 * ks + 2 * t;
                const int ra = 16 * mi + g;
                u32 ah[4], al[4];
                ah[0] = *(const u32*)&sAh[ra * KA + k0];
                ah[1] = *(const u32*)&sAh[(ra + 8) * KA + k0];
                ah[2] = *(const u32*)&sAh[ra * KA + k0 + 8];
                ah[3] = *(const u32*)&sAh[(ra + 8) * KA + k0 + 8];
                al[0] = *(const u32*)&sAl[ra * KA + k0];
                al[1] = *(const u32*)&sAl[(ra + 8) * KA + k0];
                al[2] = *(const u32*)&sAl[ra * KA + k0 + 8];
                al[3] = *(const u32*)&sAl[(ra + 8) * KA + k0 + 8];
                #pragma unroll
                for (int nt = 0; nt < 4; nt++) {
                    const int n = 32 * ns + 8 * nt + g;
                    const __nv_bfloat16* bh = &sWoH[n * KW + k0];
                    const __nv_bfloat16* bl = &sWoL[n * KW + k0];
                    const u32 bh0 = *(const u32*)bh, bh1 = *(const u32*)(bh + 8);
                    const u32 bl0 = *(const u32*)bl, bl1 = *(const u32*)(bl + 8);
                    mma_bf16(c[nt], ah, bh0, bh1);
                    mma_bf16(c[nt], ah, bl0, bl1);
                    mma_bf16(c[nt], al, bh0, bh1);
                }
            }

            float* gout = out + wbase * (S_ * E_);
            #pragma unroll
            for (int nt = 0; nt < 4; nt++) {
                const int colb = 32 * ns + 8 * nt + 2 * t;
                const float2 bb = *(const float2*)&bo[colb];
                const int row0 = 16 * mi + g;
                if (row0 < ROWS)
                    *(float2*)&gout[row0 * E_ + colb] =
                        make_float2(c[nt][0] + bb.x, c[nt][1] + bb.y);
                const int row1 = row0 + 8;
                if (row1 < ROWS)
                    *(float2*)&gout[row1 * E_ + colb] =
                        make_float2(c[nt][2] + bb.x, c[nt][3] + bb.y);
            }
        }
        // loop-top __syncthreads protects sAh/sAl before next X load
    }
}

extern "C" void kernel_launch(void* const* d_in, const int* in_sizes, int n_in,
                              void* d_out, int out_size)
{
    const float* X    = (const float*)d_in[0];
    const float* Wqkv = (const float*)d_in[1];
    const float* bqkv = (const float*)d_in[2];
    const float* Wo   = (const float*)d_in[3];
    const float* bo   = (const float*)d_in[4];
    const float* posb = (const float*)d_in[5];
    float* out = (float*)d_out;

    // split weights to bf16 hi/lo, padded k-major (same stream -> ordered)
    prep_split<<<(N3_ * KW + 255) / 256, 256>>>(Wqkv, Wo);

    cudaFuncSetAttribute(swin_msa_kernel,
                         cudaFuncAttributeMaxDynamicSharedMemorySize, SMEM_BYTES);

    const int n_windows = in_sizes[0] / (S_ * E_);   // 65536
    const int n_groups = n_windows / WPB;            // 16384
    swin_msa_kernel<<<1024, NTHREADS, SMEM_BYTES>>>(X, bqkv, bo, posb, out, n_groups);
}